// round 12
// baseline (speedup 1.0000x reference)
#include <cuda_runtime.h>
#include <cuda_fp16.h>
#include <cstdint>

// Fixed problem shape
#define NB 8
#define HW (640*640)        // 409600
#define NL 33
#define NREP 32             // accumulator replicas (same-address chain spreading)
#define TPB 256
#define PPT 4
#define PIX_PER_BLOCK (TPB*PPT)              // 1024
#define BLOCKS_PER_BATCH (HW/PIX_PER_BLOCK)  // 400 exact
#define GRID_MAIN (NB*BLOCKS_PER_BATCH)      // 3200
// phase2: 8 px/thread
#define PPT2 8
#define PIX_PER_BLOCK2 (TPB*PPT2)            // 2048
#define BLOCKS_PER_BATCH2 (HW/PIX_PER_BLOCK2) // 200 exact
#define GRID2 (NB*BLOCKS_PER_BATCH2)         // 1600
#define FULLM 0xFFFFFFFFu

struct alignas(256) Accum {
    float4   sums;     // kernel-masked embedding sums
    unsigned cnt;      // (cnt_i << 16) | cnt_k
    float    pad[59];
};

// Zero-initialized at load; phase1's last block computes means and phase2
// re-zeroes accumulators -> graph replays are self-consistent.
__device__ Accum    g_acc[NREP][NB][NL];   // 2.1 MB
__device__ float4   g_mean[NB][NL];
__device__ float    g_w[NB][NL];
__device__ unsigned g_lab[NB * HW / 4];    // packed per-pixel labels (4 x u8)
__device__ uint2    g_e16[NB * HW];        // fp16 emb relay: 8 B/px = 26 MB
__device__ float    g_scalar;
__device__ unsigned g_done1, g_done2;

__device__ __forceinline__ void red_add_v4f(float4* p, float a, float b, float c, float d) {
    asm volatile("red.global.add.v4.f32 [%0], {%1, %2, %3, %4};"
                 :: "l"(p), "f"(a), "f"(b), "f"(c), "f"(d) : "memory");
}
__device__ __forceinline__ void red_add_u32(unsigned* p, unsigned v) {
    asm volatile("red.global.add.u32 [%0], %1;" :: "l"(p), "r"(v) : "memory");
}
__device__ __forceinline__ void red_add_f32(float* p, float v) {
    asm volatile("red.global.add.f32 [%0], %1;" :: "l"(p), "f"(v) : "memory");
}
__device__ __forceinline__ float sqrt_approx(float x) {
    float r; asm("sqrt.approx.f32 %0, %1;" : "=f"(r) : "f"(x)); return r;
}
__device__ __forceinline__ unsigned pack_h2(float a, float b) {
    __half2 h = __floats2half2_rn(a, b);
    return *reinterpret_cast<unsigned*>(&h);
}
__device__ __forceinline__ float2 unpack_h2(unsigned u) {
    __half2 h = *reinterpret_cast<__half2*>(&u);
    return __half22float2(h);
}

// -------- K1: segment sums/counts + label cache + fp16 emb relay + means ----
__global__ __launch_bounds__(TPB) void k_phase1(
    const float* __restrict__ emb, const int* __restrict__ inst,
    const float* __restrict__ kern, const float* __restrict__ tmk) {
    __shared__ unsigned scnt[NL];   // block count histogram: (cnt_i<<16)|cnt_k
    __shared__ int slast;

    int blk = blockIdx.x;
    int b   = blk / BLOCKS_PER_BATCH;
    int tid = threadIdx.x;
    unsigned lane = tid & 31u;
    int wid = tid >> 5;
    unsigned rep = (unsigned)(blk * (TPB / 32) + wid) & (NREP - 1);

    if (tid < NL) scnt[tid] = 0u;

    int p    = (blk - b * BLOCKS_PER_BATCH) * PIX_PER_BLOCK + tid * PPT;
    int base = b * HW + p;

    int4   iv = *reinterpret_cast<const int4*>(inst + base);
    float4 tv = *reinterpret_cast<const float4*>(tmk + base);
    float4 kv = *reinterpret_cast<const float4*>(kern + base);
    const int*   ivp = reinterpret_cast<const int*>(&iv);
    const float* tvp = reinterpret_cast<const float*>(&tv);
    const float* kvp = reinterpret_cast<const float*>(&kv);

    int  li[PPT]; bool kk[PPT]; bool anylab = false, anyk = false;
#pragma unroll
    for (int j = 0; j < PPT; j++) {
        int l = (tvp[j] > 0.5f) ? ivp[j] : 0;
        if ((unsigned)l >= NL) l = 0;
        li[j] = l;
        kk[j] = (kvp[j] > 0.5f) && (l != 0);
        anyk   |= kk[j];
        anylab |= (l != 0);
    }

    // Labels for phase 2.
    g_lab[base >> 2] = (unsigned)li[0] | ((unsigned)li[1] << 8)
                     | ((unsigned)li[2] << 16) | ((unsigned)li[3] << 24);

    // emb needed if any pixel has nonzero label (feeds sums and/or phase2).
    float4 e0 = make_float4(0.f,0.f,0.f,0.f), e1 = e0, e2 = e0, e3 = e0;
    if (anylab) {
        const float* eb = emb + (size_t)b * 4 * HW + p;
        e0 = *reinterpret_cast<const float4*>(eb);
        e1 = *reinterpret_cast<const float4*>(eb + HW);
        e2 = *reinterpret_cast<const float4*>(eb + 2 * HW);
        e3 = *reinterpret_cast<const float4*>(eb + 3 * HW);
    }
    const float* c0 = reinterpret_cast<const float*>(&e0);
    const float* c1 = reinterpret_cast<const float*>(&e1);
    const float* c2 = reinterpret_cast<const float*>(&e2);
    const float* c3 = reinterpret_cast<const float*>(&e3);

    // fp16 relay for phase2: 4 px -> 32 B (2 x uint4). Skipped for all-zero
    // groups; phase2 predicates on li!=0 so stale data there is harmless.
    if (anylab) {
        uint4 r0, r1;
        r0.x = pack_h2(c0[0], c1[0]); r0.y = pack_h2(c2[0], c3[0]);
        r0.z = pack_h2(c0[1], c1[1]); r0.w = pack_h2(c2[1], c3[1]);
        r1.x = pack_h2(c0[2], c1[2]); r1.y = pack_h2(c2[2], c3[2]);
        r1.z = pack_h2(c0[3], c1[3]); r1.w = pack_h2(c2[3], c3[3]);
        uint4* dst = reinterpret_cast<uint4*>(&g_e16[base]);
        dst[0] = r0; dst[1] = r1;
    }

    __syncthreads();   // scnt zeroed

#pragma unroll
    for (int j = 0; j < PPT; j++) {
        unsigned mm = __match_any_sync(FULLM, li[j]);
        unsigned kb = __ballot_sync(FULLM, kk[j]);
        if (li[j] != 0 && (unsigned)(__ffs(mm) - 1) == lane)
            atomicAdd(&scnt[li[j]], ((unsigned)__popc(mm) << 16)
                                    | (unsigned)__popc(mm & kb));
        if (kk[j])
            red_add_v4f(&g_acc[rep][b][li[j]].sums, c0[j], c1[j], c2[j], c3[j]);
    }

    __syncthreads();
    if (tid >= 1 && tid < NL) {
        unsigned v = scnt[tid];
        if (v) red_add_u32(&g_acc[(unsigned)(blk + tid) & (NREP - 1)][b][tid].cnt, v);
    }

    // ---- last-finishing block computes means + weights (k_mean folded) ----
    __threadfence();       // publish this thread's REDs/stores
    __syncthreads();
    if (tid == 0) slast = (atomicAdd(&g_done1, 1u) == (unsigned)(GRID_MAIN - 1)) ? 1 : 0;
    __syncthreads();
    if (!slast) return;
    __threadfence();       // acquire all blocks' REDs

    for (int i = tid; i < NB * NL; i += TPB) {
        int bb = i / NL, l = i - bb * NL;
        float sx = 0.f, sy = 0.f, sz = 0.f, sww = 0.f;
        unsigned c = 0u;
#pragma unroll
        for (int r = 0; r < NREP; r++) {
            const Accum& a = g_acc[r][bb][l];
            sx += a.sums.x; sy += a.sums.y; sz += a.sums.z; sww += a.sums.w;
            c += a.cnt;
        }
        float cnt_k = (float)(c & 0xFFFFu);
        float cnt_i = (float)(c >> 16);
        float inv = (l == 0) ? 0.f : (1.f / fmaxf(cnt_k, 1.f));
        g_mean[bb][l] = make_float4(sx * inv, sy * inv, sz * inv, sww * inv);
        g_w[bb][l]    = (l == 0) ? 0.f : (1.f / (32.f * fmaxf(cnt_i, 1.f)));
    }
    if (tid == 0) { g_done1 = 0u; g_scalar = 0.f; }
}

// -------- K2: per-pixel loss from fp16 relay + epilogue + distributed reset --
__global__ __launch_bounds__(TPB) void k_phase2(float* __restrict__ out) {
    __shared__ float4 smean[NL];
    __shared__ float  swt[NL];
    __shared__ float  swred[8];
    __shared__ int    slast;

    int blk = blockIdx.x;
    int b   = blk / BLOCKS_PER_BATCH2;
    int tid = threadIdx.x;
    if (tid < NL) { smean[tid] = g_mean[b][tid]; swt[tid] = g_w[b][tid]; }

    // Distributed accumulator reset for the next replay (6 structs per block;
    // nothing in phase2 reads g_acc, so ordering is free).
    if (tid < 6) {
        int idx = blk * 6 + tid;
        if (idx < NREP * NB * NL) {
            Accum* a = &(&g_acc[0][0][0])[idx];
            a->sums = make_float4(0.f, 0.f, 0.f, 0.f);
            a->cnt  = 0u;
        }
    }
    __syncthreads();

    int p    = (blk - b * BLOCKS_PER_BATCH2) * PIX_PER_BLOCK2 + tid * PPT2;
    int base = b * HW + p;

    // Front-batched: 1 uint2 (8 labels) + 4 uint4 (8 px fp16 emb, 64 B dense).
    uint2 lab2 = *reinterpret_cast<const uint2*>(&g_lab[base >> 2]);
    const uint4* src = reinterpret_cast<const uint4*>(&g_e16[base]);
    uint4 q[4];
#pragma unroll
    for (int g = 0; g < 4; g++) q[g] = src[g];

    float acc = 0.f;
#pragma unroll
    for (int g = 0; g < 4; g++) {        // uint4 g holds pixels 2g, 2g+1
#pragma unroll
        for (int h = 0; h < 2; h++) {
            int j = 2 * g + h;
            unsigned lw = (j < 4) ? lab2.x : lab2.y;
            int li = (int)((lw >> (8 * (j & 3))) & 0xFFu);
            float2 ab = unpack_h2(h ? q[g].z : q[g].x);
            float2 cd = unpack_h2(h ? q[g].w : q[g].y);
            float4 m = smean[li];
            float dx = ab.x - m.x, dy = ab.y - m.y;
            float dz = cd.x - m.z, dw = cd.y - m.w;
            float s  = dx*dx + dy*dy + dz*dz + dw*dw;
            float tt = fmaxf(sqrt_approx(s) - 0.5f, 0.f);   // DELTA_V = 0.5
            float val = __logf(fmaf(tt, tt, 1.f));
            if (li) acc = fmaf(swt[li], val, acc);  // predicated: stale-safe
        }
    }

    // Block reduction -> ONE global RED per block (1600 total).
#pragma unroll
    for (int off = 16; off; off >>= 1)
        acc += __shfl_down_sync(FULLM, acc, off);
    if ((tid & 31) == 0) swred[tid >> 5] = acc;
    __syncthreads();
    if (tid == 0) {
        float s2 = 0.f;
#pragma unroll
        for (int w = 0; w < 8; w++) s2 += swred[w];
        red_add_f32(&g_scalar, s2);
        __threadfence();
        slast = (atomicAdd(&g_done2, 1u) == (unsigned)(GRID2 - 1)) ? 1 : 0;
    }
    __syncthreads();
    if (!slast) return;

    // ---------- epilogue (last block): l_dis + l_reg, write out --------------
    __threadfence();
    __shared__ float sred2[TPB];
    float a2 = 0.f;
    for (int i = tid; i < NB * 32; i += TPB) {            // l_reg
        int bb = i >> 5, l = (i & 31) + 1;
        float4 m = g_mean[bb][l];
        float n = sqrtf(m.x*m.x + m.y*m.y + m.z*m.z + m.w*m.w);
        a2 += logf(n + 1.f) * (0.001f / 33.0f);
    }
    for (int idx = tid; idx < NB * 32 * 32; idx += TPB) { // l_dis, i != j
        int bb = idx >> 10, rr = idx & 1023, i = rr >> 5, j = rr & 31;
        if (i != j) {
            float4 mi = g_mean[bb][i + 1], mj = g_mean[bb][j + 1];
            float dx = mi.x - mj.x, dy = mi.y - mj.y;
            float dz = mi.z - mj.z, dw = mi.w - mj.w;
            float pd = sqrtf(dx*dx + dy*dy + dz*dz + dw*dw);
            float tt = fmaxf(3.0f - pd, 0.f);             // 2*DELTA_D
            a2 += logf(fmaf(tt, tt, 1.f)) * (1.0f / 992.0f);
        }
    }
    sred2[tid] = a2;
    __syncthreads();
    for (int s = TPB / 2; s > 0; s >>= 1) {
        if (tid < s) sred2[tid] += sred2[tid + s];
        __syncthreads();
    }
    if (tid == 0) {
        float S = *(volatile float*)&g_scalar;   // l_agg (weights folded in)
        out[0] = (S + sred2[0]) * (1.0f / NB);   // LOSS_WEIGHT = 1
        g_done2 = 0u;                            // reset ticket for next replay
    }
}

// ---------------- launch: 2 kernels ------------------------------------------
extern "C" void kernel_launch(void* const* d_in, const int* in_sizes, int n_in,
                              void* d_out, int out_size) {
    (void)in_sizes; (void)n_in; (void)out_size;
    const float* emb  = (const float*)d_in[0];
    const int*   inst = (const int*)d_in[1];
    const float* kern = (const float*)d_in[2];
    const float* tmk  = (const float*)d_in[3];
    float* out = (float*)d_out;

    k_phase1<<<GRID_MAIN, TPB>>>(emb, inst, kern, tmk);
    k_phase2<<<GRID2, TPB>>>(out);
}

// round 13
// speedup vs baseline: 1.1404x; 1.1404x over previous
#include <cuda_runtime.h>
#include <cstdint>

// Fixed problem shape
#define NB 8
#define HW (640*640)        // 409600
#define NL 33
#define NREP 32             // accumulator replicas (same-address chain spreading)
#define TPB 256
#define PPT 4
#define PIX_PER_BLOCK (TPB*PPT)              // 1024
#define BLOCKS_PER_BATCH (HW/PIX_PER_BLOCK)  // 400 exact
#define GRID_MAIN (NB*BLOCKS_PER_BATCH)      // 3200
#define FULLM 0xFFFFFFFFu

// 256B-aligned: consecutive hot accumulators differ in addr bits >=8 -> spread
// across L2 slices (bit 7 transparent in the slice hash).
struct alignas(256) Accum {
    float4   sums;     // kernel-masked embedding sums
    unsigned cnt;      // (cnt_i << 16) | cnt_k
    float    pad[59];
};

// Zero-initialized at load; phase1's last block computes means + resets its
// ticket, phase2 re-zeroes g_acc distributed -> graph replays self-consistent.
__device__ Accum    g_acc[NREP][NB][NL];   // 2.1 MB
__device__ float4   g_mean[NB][NL];
__device__ float    g_w[NB][NL];
__device__ unsigned g_lab[NB * HW / 4];    // packed per-pixel labels (4 x u8)
__device__ float    g_scalar;
__device__ unsigned g_done1, g_done2;

__device__ __forceinline__ void red_add_v4f(float4* p, float a, float b, float c, float d) {
    asm volatile("red.global.add.v4.f32 [%0], {%1, %2, %3, %4};"
                 :: "l"(p), "f"(a), "f"(b), "f"(c), "f"(d) : "memory");
}
__device__ __forceinline__ void red_add_u32(unsigned* p, unsigned v) {
    asm volatile("red.global.add.u32 [%0], %1;" :: "l"(p), "r"(v) : "memory");
}
__device__ __forceinline__ void red_add_f32(float* p, float v) {
    asm volatile("red.global.add.f32 [%0], %1;" :: "l"(p), "f"(v) : "memory");
}
__device__ __forceinline__ float sqrt_approx(float x) {
    float r; asm("sqrt.approx.f32 %0, %1;" : "=f"(r) : "f"(x)); return r;
}

// -------- K1: segment sums/counts + label cache; last block folds means ------
__global__ __launch_bounds__(TPB) void k_phase1(
    const float* __restrict__ emb, const int* __restrict__ inst,
    const float* __restrict__ kern, const float* __restrict__ tmk) {
    __shared__ unsigned scnt[NL];   // block count histogram: (cnt_i<<16)|cnt_k
    __shared__ int slast;

    int blk = blockIdx.x;
    int b   = blk / BLOCKS_PER_BATCH;
    int tid = threadIdx.x;
    unsigned lane = tid & 31u;
    int wid = tid >> 5;
    unsigned rep = (unsigned)(blk * (TPB / 32) + wid) & (NREP - 1);

    if (tid < NL) scnt[tid] = 0u;

    int p    = (blk - b * BLOCKS_PER_BATCH) * PIX_PER_BLOCK + tid * PPT;
    int base = b * HW + p;

    int4   iv = *reinterpret_cast<const int4*>(inst + base);
    float4 tv = *reinterpret_cast<const float4*>(tmk + base);
    float4 kv = *reinterpret_cast<const float4*>(kern + base);
    const int*   ivp = reinterpret_cast<const int*>(&iv);
    const float* tvp = reinterpret_cast<const float*>(&tv);
    const float* kvp = reinterpret_cast<const float*>(&kv);

    int  li[PPT]; bool kk[PPT]; bool anyk = false;
#pragma unroll
    for (int j = 0; j < PPT; j++) {
        int l = (tvp[j] > 0.5f) ? ivp[j] : 0;
        if ((unsigned)l >= NL) l = 0;
        li[j] = l;
        kk[j] = (kvp[j] > 0.5f) && (l != 0);
        anyk |= kk[j];
    }

    // Labels for phase 2 (it re-reads emb but not inst/tmk/kern).
    g_lab[base >> 2] = (unsigned)li[0] | ((unsigned)li[1] << 8)
                     | ((unsigned)li[2] << 16) | ((unsigned)li[3] << 24);

    // emb only feeds kernel-masked sums: skip loads when no pixel qualifies.
    float4 e0 = make_float4(0.f,0.f,0.f,0.f), e1 = e0, e2 = e0, e3 = e0;
    if (anyk) {
        const float* eb = emb + (size_t)b * 4 * HW + p;
        e0 = *reinterpret_cast<const float4*>(eb);
        e1 = *reinterpret_cast<const float4*>(eb + HW);
        e2 = *reinterpret_cast<const float4*>(eb + 2 * HW);
        e3 = *reinterpret_cast<const float4*>(eb + 3 * HW);
    }
    const float* c0 = reinterpret_cast<const float*>(&e0);
    const float* c1 = reinterpret_cast<const float*>(&e1);
    const float* c2 = reinterpret_cast<const float*>(&e2);
    const float* c3 = reinterpret_cast<const float*>(&e3);

    __syncthreads();   // scnt zeroed

#pragma unroll
    for (int j = 0; j < PPT; j++) {
        // Counts: warp-aggregate into the block smem histogram; one leader
        // ATOMS per distinct label per slot.
        unsigned mm = __match_any_sync(FULLM, li[j]);
        unsigned kb = __ballot_sync(FULLM, kk[j]);
        if (li[j] != 0 && (unsigned)(__ffs(mm) - 1) == lane)
            atomicAdd(&scnt[li[j]], ((unsigned)__popc(mm) << 16)
                                    | (unsigned)__popc(mm & kb));
        // Sums: per masked pixel; contention handled by NREP=32 replicas.
        if (kk[j])
            red_add_v4f(&g_acc[rep][b][li[j]].sums, c0[j], c1[j], c2[j], c3[j]);
    }

    __syncthreads();
    // Flush counts: 32 REDs per block.
    if (tid >= 1 && tid < NL) {
        unsigned v = scnt[tid];
        if (v) red_add_u32(&g_acc[(unsigned)(blk + tid) & (NREP - 1)][b][tid].cnt, v);
    }

    // ---- last-finishing block computes means + weights (k_mean folded) -----
    __threadfence();
    __syncthreads();
    if (tid == 0) slast = (atomicAdd(&g_done1, 1u) == (unsigned)(GRID_MAIN - 1)) ? 1 : 0;
    __syncthreads();
    if (!slast) return;
    __threadfence();   // acquire all blocks' REDs

    for (int i = tid; i < NB * NL; i += TPB) {
        int bb = i / NL, l = i - bb * NL;
        float sx = 0.f, sy = 0.f, sz = 0.f, sww = 0.f;
        unsigned c = 0u;
#pragma unroll
        for (int r = 0; r < NREP; r++) {
            const Accum& a = g_acc[r][bb][l];
            sx += a.sums.x; sy += a.sums.y; sz += a.sums.z; sww += a.sums.w;
            c += a.cnt;
        }
        float cnt_k = (float)(c & 0xFFFFu);
        float cnt_i = (float)(c >> 16);
        float inv = (l == 0) ? 0.f : (1.f / fmaxf(cnt_k, 1.f));
        g_mean[bb][l] = make_float4(sx * inv, sy * inv, sz * inv, sww * inv);
        g_w[bb][l]    = (l == 0) ? 0.f : (1.f / (32.f * fmaxf(cnt_i, 1.f)));
    }
    if (tid == 0) { g_done1 = 0u; g_scalar = 0.f; }
}

// -------- K2: per-pixel loss (reversed order: ride L2 retention) + epilogue --
__global__ __launch_bounds__(TPB) void k_phase2(
    const float* __restrict__ emb, float* __restrict__ out) {
    __shared__ float4 smean[NL];
    __shared__ float  swt[NL];
    __shared__ float  swred[8];
    __shared__ int    slast;

    // Reverse: phase1's most recently streamed lines (high addresses) are the
    // freshest in L2 -> read them first.
    int blk = (GRID_MAIN - 1) - (int)blockIdx.x;
    int b   = blk / BLOCKS_PER_BATCH;
    int tid = threadIdx.x;
    if (tid < NL) { smean[tid] = g_mean[b][tid]; swt[tid] = g_w[b][tid]; }

    // Distributed accumulator reset for the next replay (3 structs per block).
    if (tid < 3) {
        int idx = (int)blockIdx.x * 3 + tid;
        if (idx < NREP * NB * NL) {
            Accum* a = &(&g_acc[0][0][0])[idx];
            a->sums = make_float4(0.f, 0.f, 0.f, 0.f);
            a->cnt  = 0u;
        }
    }
    __syncthreads();

    int p    = (blk - b * BLOCKS_PER_BATCH) * PIX_PER_BLOCK + tid * PPT;
    int base = b * HW + p;

    unsigned lab = g_lab[base >> 2];
    const float* eb = emb + (size_t)b * 4 * HW + p;
    float4 e0 = *reinterpret_cast<const float4*>(eb);
    float4 e1 = *reinterpret_cast<const float4*>(eb + HW);
    float4 e2 = *reinterpret_cast<const float4*>(eb + 2 * HW);
    float4 e3 = *reinterpret_cast<const float4*>(eb + 3 * HW);
    const float* c0 = reinterpret_cast<const float*>(&e0);
    const float* c1 = reinterpret_cast<const float*>(&e1);
    const float* c2 = reinterpret_cast<const float*>(&e2);
    const float* c3 = reinterpret_cast<const float*>(&e3);

    float acc = 0.f;   // branchless: w[0]=0 kills unmasked pixels
#pragma unroll
    for (int j = 0; j < PPT; j++) {
        int li = (int)((lab >> (8 * j)) & 0xFFu);
        float4 m = smean[li];
        float wv = swt[li];
        float dx = c0[j] - m.x, dy = c1[j] - m.y;
        float dz = c2[j] - m.z, dw = c3[j] - m.w;
        float s  = dx*dx + dy*dy + dz*dz + dw*dw;
        float tt = fmaxf(sqrt_approx(s) - 0.5f, 0.f);     // DELTA_V = 0.5
        acc = fmaf(wv, __logf(fmaf(tt, tt, 1.f)), acc);
    }

    // Block reduction -> ONE global RED per block (3200 total).
#pragma unroll
    for (int off = 16; off; off >>= 1)
        acc += __shfl_down_sync(FULLM, acc, off);
    if ((tid & 31) == 0) swred[tid >> 5] = acc;
    __syncthreads();
    if (tid == 0) {
        float s2 = 0.f;
#pragma unroll
        for (int w = 0; w < 8; w++) s2 += swred[w];
        red_add_f32(&g_scalar, s2);
        __threadfence();
        slast = (atomicAdd(&g_done2, 1u) == (unsigned)(GRID_MAIN - 1)) ? 1 : 0;
    }
    __syncthreads();
    if (!slast) return;

    // ---------- epilogue (last block): l_dis + l_reg, write out --------------
    __threadfence();
    __shared__ float sred2[TPB];
    float a2 = 0.f;
    for (int i = tid; i < NB * 32; i += TPB) {            // l_reg
        int bb = i >> 5, l = (i & 31) + 1;
        float4 m = g_mean[bb][l];
        float n = sqrtf(m.x*m.x + m.y*m.y + m.z*m.z + m.w*m.w);
        a2 += logf(n + 1.f) * (0.001f / 33.0f);
    }
    for (int idx = tid; idx < NB * 32 * 32; idx += TPB) { // l_dis, i != j
        int bb = idx >> 10, rr = idx & 1023, i = rr >> 5, j = rr & 31;
        if (i != j) {
            float4 mi = g_mean[bb][i + 1], mj = g_mean[bb][j + 1];
            float dx = mi.x - mj.x, dy = mi.y - mj.y;
            float dz = mi.z - mj.z, dw = mi.w - mj.w;
            float pd = sqrtf(dx*dx + dy*dy + dz*dz + dw*dw);
            float tt = fmaxf(3.0f - pd, 0.f);             // 2*DELTA_D
            a2 += logf(fmaf(tt, tt, 1.f)) * (1.0f / 992.0f);
        }
    }
    sred2[tid] = a2;
    __syncthreads();
    for (int s = TPB / 2; s > 0; s >>= 1) {
        if (tid < s) sred2[tid] += sred2[tid + s];
        __syncthreads();
    }
    if (tid == 0) {
        float S = *(volatile float*)&g_scalar;   // l_agg (weights folded in)
        out[0] = (S + sred2[0]) * (1.0f / NB);   // LOSS_WEIGHT = 1
        g_done2 = 0u;                            // reset ticket for next replay
    }
}

// ---------------- launch: 2 kernels ------------------------------------------
extern "C" void kernel_launch(void* const* d_in, const int* in_sizes, int n_in,
                              void* d_out, int out_size) {
    (void)in_sizes; (void)n_in; (void)out_size;
    const float* emb  = (const float*)d_in[0];
    const int*   inst = (const int*)d_in[1];
    const float* kern = (const float*)d_in[2];
    const float* tmk  = (const float*)d_in[3];
    float* out = (float*)d_out;

    k_phase1<<<GRID_MAIN, TPB>>>(emb, inst, kern, tmk);
    k_phase2<<<GRID_MAIN, TPB>>>(emb, out);
}

// round 14
// speedup vs baseline: 1.4152x; 1.2410x over previous
#include <cuda_runtime.h>
#include <cstdint>

// Fixed problem shape
#define NB 8
#define HW (640*640)        // 409600
#define NL 33
#define NREP 32             // accumulator replicas (same-address chain spreading)
#define TPB 256
#define PPT 4
#define PIX_PER_BLOCK (TPB*PPT)              // 1024
#define BLOCKS_PER_BATCH (HW/PIX_PER_BLOCK)  // 400 exact
#define GRID_MAIN (NB*BLOCKS_PER_BATCH)      // 3200 per phase
#define GRID_ALL (2*GRID_MAIN)               // 6400: phase1 bids < phase2 bids
#define FULLM 0xFFFFFFFFu

// 256B-aligned: consecutive hot accumulators differ in addr bits >=8 -> spread
// across L2 slices (bit 7 transparent in the slice hash).
struct alignas(256) Accum {
    float4   sums;     // kernel-masked embedding sums
    unsigned cnt;      // (cnt_i << 16) | cnt_k
    float    pad[59];
};

// Per-batch means, padded/aligned so no 128B line crosses batches (an SM's L1
// must never hold a line of a not-yet-ready batch).
struct alignas(128) MeanBlk {
    float4 m[NL];      // 528 B
    float  w[NL];      // 132 B
    float  pad[27];    // -> 768 B
};

// Zero-initialized at load; epilogue resets all tickets/flags; phase2 blocks
// reset their batch's g_acc slice -> graph replays are self-consistent.
__device__ Accum    g_acc[NREP][NB][NL];   // 2.1 MB
__device__ MeanBlk  g_mb[NB];
__device__ unsigned g_lab[NB * HW / 4];    // packed per-pixel labels (4 x u8)
__device__ volatile unsigned g_ready[NB];  // per-batch means-published flag
__device__ unsigned g_done1[NB];           // per-batch phase1 ticket
__device__ unsigned g_done2;               // global phase2 ticket
__device__ float    g_scalar;

__device__ __forceinline__ void red_add_v4f(float4* p, float a, float b, float c, float d) {
    asm volatile("red.global.add.v4.f32 [%0], {%1, %2, %3, %4};"
                 :: "l"(p), "f"(a), "f"(b), "f"(c), "f"(d) : "memory");
}
__device__ __forceinline__ void red_add_u32(unsigned* p, unsigned v) {
    asm volatile("red.global.add.u32 [%0], %1;" :: "l"(p), "r"(v) : "memory");
}
__device__ __forceinline__ void red_add_f32(float* p, float v) {
    asm volatile("red.global.add.f32 [%0], %1;" :: "l"(p), "f"(v) : "memory");
}
__device__ __forceinline__ float sqrt_approx(float x) {
    float r; asm("sqrt.approx.f32 %0, %1;" : "=f"(r) : "f"(x)); return r;
}

// ---------------- phase 1 body: one 1024-px tile of batch b ------------------
__device__ __forceinline__ void phase1_body(
    int blk, const float* __restrict__ emb, const int* __restrict__ inst,
    const float* __restrict__ kern, const float* __restrict__ tmk) {
    __shared__ unsigned scnt[NL];
    __shared__ int slast;

    int b   = blk / BLOCKS_PER_BATCH;
    int tid = threadIdx.x;
    unsigned lane = tid & 31u;
    int wid = tid >> 5;
    unsigned rep = (unsigned)(blk * (TPB / 32) + wid) & (NREP - 1);

    if (tid < NL) scnt[tid] = 0u;

    int p    = (blk - b * BLOCKS_PER_BATCH) * PIX_PER_BLOCK + tid * PPT;
    int base = b * HW + p;

    int4   iv = *reinterpret_cast<const int4*>(inst + base);
    float4 tv = *reinterpret_cast<const float4*>(tmk + base);
    float4 kv = *reinterpret_cast<const float4*>(kern + base);
    const int*   ivp = reinterpret_cast<const int*>(&iv);
    const float* tvp = reinterpret_cast<const float*>(&tv);
    const float* kvp = reinterpret_cast<const float*>(&kv);

    int  li[PPT]; bool kk[PPT]; bool anyk = false;
#pragma unroll
    for (int j = 0; j < PPT; j++) {
        int l = (tvp[j] > 0.5f) ? ivp[j] : 0;
        if ((unsigned)l >= NL) l = 0;
        li[j] = l;
        kk[j] = (kvp[j] > 0.5f) && (l != 0);
        anyk |= kk[j];
    }

    // Labels for phase 2.
    g_lab[base >> 2] = (unsigned)li[0] | ((unsigned)li[1] << 8)
                     | ((unsigned)li[2] << 16) | ((unsigned)li[3] << 24);

    // emb only feeds kernel-masked sums: skip loads when no pixel qualifies.
    float4 e0 = make_float4(0.f,0.f,0.f,0.f), e1 = e0, e2 = e0, e3 = e0;
    if (anyk) {
        const float* eb = emb + (size_t)b * 4 * HW + p;
        e0 = *reinterpret_cast<const float4*>(eb);
        e1 = *reinterpret_cast<const float4*>(eb + HW);
        e2 = *reinterpret_cast<const float4*>(eb + 2 * HW);
        e3 = *reinterpret_cast<const float4*>(eb + 3 * HW);
    }
    const float* c0 = reinterpret_cast<const float*>(&e0);
    const float* c1 = reinterpret_cast<const float*>(&e1);
    const float* c2 = reinterpret_cast<const float*>(&e2);
    const float* c3 = reinterpret_cast<const float*>(&e3);

    __syncthreads();   // scnt zeroed

#pragma unroll
    for (int j = 0; j < PPT; j++) {
        unsigned mm = __match_any_sync(FULLM, li[j]);   // warp-aggregate counts
        unsigned kb = __ballot_sync(FULLM, kk[j]);
        if (li[j] != 0 && (unsigned)(__ffs(mm) - 1) == lane)
            atomicAdd(&scnt[li[j]], ((unsigned)__popc(mm) << 16)
                                    | (unsigned)__popc(mm & kb));
        if (kk[j])
            red_add_v4f(&g_acc[rep][b][li[j]].sums, c0[j], c1[j], c2[j], c3[j]);
    }

    __syncthreads();
    if (tid >= 1 && tid < NL) {
        unsigned v = scnt[tid];
        if (v) red_add_u32(&g_acc[(unsigned)(blk + tid) & (NREP - 1)][b][tid].cnt, v);
    }

    // ---- per-batch ticket: last block of batch b computes means(b) ----------
    __threadfence();
    __syncthreads();
    if (tid == 0)
        slast = (atomicAdd(&g_done1[b], 1u) == (unsigned)(BLOCKS_PER_BATCH - 1)) ? 1 : 0;
    __syncthreads();
    if (!slast) return;
    __threadfence();   // acquire all batch-b REDs

    for (int l = tid; l < NL; l += TPB) {
        float sx = 0.f, sy = 0.f, sz = 0.f, sww = 0.f;
        unsigned c = 0u;
#pragma unroll
        for (int r = 0; r < NREP; r++) {
            const Accum& a = g_acc[r][b][l];
            sx += a.sums.x; sy += a.sums.y; sz += a.sums.z; sww += a.sums.w;
            c += a.cnt;
        }
        float cnt_k = (float)(c & 0xFFFFu);
        float cnt_i = (float)(c >> 16);
        float inv = (l == 0) ? 0.f : (1.f / fmaxf(cnt_k, 1.f));
        g_mb[b].m[l] = make_float4(sx * inv, sy * inv, sz * inv, sww * inv);
        g_mb[b].w[l] = (l == 0) ? 0.f : (1.f / (32.f * fmaxf(cnt_i, 1.f)));
    }
    __threadfence();   // publish means before flag
    __syncthreads();
    if (tid == 0) atomicExch((unsigned*)&g_ready[b], 1u);
}

// ---------------- phase 2 body: loss tile + epilogue -------------------------
__device__ __forceinline__ void phase2_body(
    int blk, const float* __restrict__ emb, float* __restrict__ out) {
    __shared__ float4 smean[NL];
    __shared__ float  swt[NL];
    __shared__ float  swred[8];
    __shared__ int    slast;

    int b   = blk / BLOCKS_PER_BATCH;
    int tid = threadIdx.x;

    // Wait for means(b). Phase1 bids all precede phase2 bids, so every phase1
    // block is dispatched before any phase2 block -> guaranteed progress.
    if (tid == 0) {
        while (g_ready[b] == 0u) __nanosleep(64);
    }
    __syncthreads();
    __threadfence();   // acquire means

    if (tid < NL) { smean[tid] = g_mb[b].m[tid]; swt[tid] = g_mb[b].w[tid]; }

    // Distributed reset of batch b's accumulator slice for the next replay
    // (means(b) already consumed; 3 structs x 400 blocks covers 1056).
    {
        int r0 = (blk - b * BLOCKS_PER_BATCH) * 3;
#pragma unroll
        for (int k = 0; k < 3; k++) {
            int s = r0 + k;
            if (s < NREP * NL) {
                Accum* a = &g_acc[s / NL][b][s % NL];
                a->sums = make_float4(0.f, 0.f, 0.f, 0.f);
                a->cnt  = 0u;
            }
        }
    }
    __syncthreads();

    int p    = (blk - b * BLOCKS_PER_BATCH) * PIX_PER_BLOCK + tid * PPT;
    int base = b * HW + p;

    unsigned lab = g_lab[base >> 2];
    const float* eb = emb + (size_t)b * 4 * HW + p;
    float4 e0 = *reinterpret_cast<const float4*>(eb);
    float4 e1 = *reinterpret_cast<const float4*>(eb + HW);
    float4 e2 = *reinterpret_cast<const float4*>(eb + 2 * HW);
    float4 e3 = *reinterpret_cast<const float4*>(eb + 3 * HW);
    const float* c0 = reinterpret_cast<const float*>(&e0);
    const float* c1 = reinterpret_cast<const float*>(&e1);
    const float* c2 = reinterpret_cast<const float*>(&e2);
    const float* c3 = reinterpret_cast<const float*>(&e3);

    float acc = 0.f;   // branchless: w[0]=0 kills unmasked pixels
#pragma unroll
    for (int j = 0; j < PPT; j++) {
        int li = (int)((lab >> (8 * j)) & 0xFFu);
        float4 m = smean[li];
        float wv = swt[li];
        float dx = c0[j] - m.x, dy = c1[j] - m.y;
        float dz = c2[j] - m.z, dw = c3[j] - m.w;
        float s  = dx*dx + dy*dy + dz*dz + dw*dw;
        float tt = fmaxf(sqrt_approx(s) - 0.5f, 0.f);     // DELTA_V = 0.5
        acc = fmaf(wv, __logf(fmaf(tt, tt, 1.f)), acc);
    }

#pragma unroll
    for (int off = 16; off; off >>= 1)
        acc += __shfl_down_sync(FULLM, acc, off);
    if ((tid & 31) == 0) swred[tid >> 5] = acc;
    __syncthreads();
    if (tid == 0) {
        float s2 = 0.f;
#pragma unroll
        for (int w = 0; w < 8; w++) s2 += swred[w];
        red_add_f32(&g_scalar, s2);
        __threadfence();
        slast = (atomicAdd(&g_done2, 1u) == (unsigned)(GRID_MAIN - 1)) ? 1 : 0;
    }
    __syncthreads();
    if (!slast) return;

    // ---------- epilogue: l_dis + l_reg, write out, reset tickets ------------
    __threadfence();
    __shared__ float sred2[TPB];
    float a2 = 0.f;
    for (int i = tid; i < NB * 32; i += TPB) {            // l_reg
        int bb = i >> 5, l = (i & 31) + 1;
        float4 m = g_mb[bb].m[l];
        float n = sqrtf(m.x*m.x + m.y*m.y + m.z*m.z + m.w*m.w);
        a2 += logf(n + 1.f) * (0.001f / 33.0f);
    }
    for (int idx = tid; idx < NB * 32 * 32; idx += TPB) { // l_dis, i != j
        int bb = idx >> 10, rr = idx & 1023, i = rr >> 5, j = rr & 31;
        if (i != j) {
            float4 mi = g_mb[bb].m[i + 1], mj = g_mb[bb].m[j + 1];
            float dx = mi.x - mj.x, dy = mi.y - mj.y;
            float dz = mi.z - mj.z, dw = mi.w - mj.w;
            float pd = sqrtf(dx*dx + dy*dy + dz*dz + dw*dw);
            float tt = fmaxf(3.0f - pd, 0.f);             // 2*DELTA_D
            a2 += logf(fmaf(tt, tt, 1.f)) * (1.0f / 992.0f);
        }
    }
    sred2[tid] = a2;
    __syncthreads();
    for (int s = TPB / 2; s > 0; s >>= 1) {
        if (tid < s) sred2[tid] += sred2[tid + s];
        __syncthreads();
    }
    if (tid == 0) {
        float S = *(volatile float*)&g_scalar;   // l_agg (weights folded in)
        out[0] = (S + sred2[0]) * (1.0f / NB);   // LOSS_WEIGHT = 1
        g_done2 = 0u;
        g_scalar = 0.f;
    }
    if (tid < NB) { g_done1[tid] = 0u; *(unsigned*)&g_ready[tid] = 0u; }
}

// ---------------- single fused launch ----------------------------------------
__global__ __launch_bounds__(TPB) void k_all(
    const float* __restrict__ emb, const int* __restrict__ inst,
    const float* __restrict__ kern, const float* __restrict__ tmk,
    float* __restrict__ out) {
    int bid = (int)blockIdx.x;
    if (bid < GRID_MAIN)
        phase1_body(bid, emb, inst, kern, tmk);
    else
        phase2_body(bid - GRID_MAIN, emb, out);
}

extern "C" void kernel_launch(void* const* d_in, const int* in_sizes, int n_in,
                              void* d_out, int out_size) {
    (void)in_sizes; (void)n_in; (void)out_size;
    const float* emb  = (const float*)d_in[0];
    const int*   inst = (const int*)d_in[1];
    const float* kern = (const float*)d_in[2];
    const float* tmk  = (const float*)d_in[3];
    float* out = (float*)d_out;

    k_all<<<GRID_ALL, TPB>>>(emb, inst, kern, tmk, out);
}